// round 13
// baseline (speedup 1.0000x reference)
#include <cuda_runtime.h>
#include <cuda_fp16.h>
#include <stdint.h>

// ---------------- problem constants ----------------
#define N_PTS   131072
#define K_RAW   585            // 9 * 65 (Y x [h,1] outer product)
#define NCHUNK  19             // 19 * 32 = 608 = K padded
#define HLEN    65

// ---------------- smem layout ----------------
// B: [buf2][part2][32 k][528B]  (528B pitch: conflict-free ldmatrix.trans)
// A: [buf2][part2][128 m][80B]  (80B pitch: conflict-free ldmatrix)
#define BP      528            // B row pitch bytes (264 halves)
#define B_PART  16896          // 32*528
#define B_CHNK  33792          // 2 parts
#define AP      80
#define A_PART  10240          // 128*80
#define A_CHNK  20480
#define SM_B    0              // 2*33792 = 67584
#define SM_A    67584          // 2*20480 = 40960
#define SM_H    108544         // fp32 [128][66] = 33792
#define SM_Y    142336         // fp32 [128][12] = 6144
#define SM_RAD  148480         // fp32 [128]     = 512
#define SM_TOTAL 148992

// ---------------- persistent scratch ----------------
// C matrix, fp16 hi/lo split, [chunk19][part2][32 k][264 halves(=528B)]
__device__ __align__(16) __half g_C[NCHUNK * 2 * 32 * 264];
__device__ float g_k2[256];

// ---------------- PTX helpers ----------------
__device__ __forceinline__ uint32_t smem_u32(const void* p) {
    uint32_t a;
    asm("{ .reg .u64 t; cvta.to.shared.u64 t, %1; cvt.u32.u64 %0, t; }" : "=r"(a) : "l"(p));
    return a;
}
__device__ __forceinline__ uint32_t hpack(__half a, __half b) {  // a -> low half
    return (uint32_t)__half_as_ushort(a) | ((uint32_t)__half_as_ushort(b) << 16);
}
#define CP16(dst, src) asm volatile("cp.async.cg.shared.global [%0], [%1], 16;" :: "r"(dst), "l"(src) : "memory")
#define CP_COMMIT()    asm volatile("cp.async.commit_group;" ::: "memory")
#define CP_WAIT0()     asm volatile("cp.async.wait_group 0;" ::: "memory")

#define LDSM4(r, a) \
    asm volatile("ldmatrix.sync.aligned.m8n8.x4.shared.b16 {%0,%1,%2,%3}, [%4];" \
        : "=r"((r)[0]), "=r"((r)[1]), "=r"((r)[2]), "=r"((r)[3]) : "r"(a))
#define LDSM4T(r, a) \
    asm volatile("ldmatrix.sync.aligned.m8n8.x4.trans.shared.b16 {%0,%1,%2,%3}, [%4];" \
        : "=r"((r)[0]), "=r"((r)[1]), "=r"((r)[2]), "=r"((r)[3]) : "r"(a))
#define MMA(d, a, b0v, b1v) \
    asm volatile("mma.sync.aligned.m16n8k16.row.col.f32.f16.f16.f32 " \
        "{%0,%1,%2,%3},{%4,%5,%6,%7},{%8,%9},{%0,%1,%2,%3};" \
        : "+f"((d)[0]), "+f"((d)[1]), "+f"((d)[2]), "+f"((d)[3]) \
        : "r"((a)[0]), "r"((a)[1]), "r"((a)[2]), "r"((a)[3]), "r"(b0v), "r"(b1v))

// ---------------- prep kernels ----------------
// C[p, y*65+j] = sum_w W2[j,w]*M1[p, y*96+w]  (j<64);  j==64 -> b2 row.
// Stored fp16 hi/lo, [k][n=p] layout, 528B pitch, chunked by 32 k.
__global__ void prep_C_kernel(const float* __restrict__ M1,
                              const float* __restrict__ W2,
                              const float* __restrict__ b2) {
    __shared__ float sW2[64 * 96];
    __shared__ float sb2[96];
    __shared__ float sM1[864];
    const int p = blockIdx.x;        // 0..255
    const int t = threadIdx.x;       // 0..607
    for (int i = t; i < 64 * 96; i += 608) sW2[i] = W2[i];
    if (t < 96) sb2[t] = b2[t];
    for (int i = t; i < 864; i += 608) sM1[i] = M1[p * 864 + i];
    __syncthreads();
    const int k = t;                 // 0..607
    float v = 0.0f;
    if (k < K_RAW) {
        const int y = k / HLEN, j = k - y * HLEN;
        const float* m = sM1 + y * 96;
        const float* w = (j < 64) ? (sW2 + j * 96) : sb2;
        #pragma unroll 8
        for (int wi = 0; wi < 96; wi++) v += w[wi] * m[wi];
    }
    __half hi = __float2half_rn(v);
    __half lo = __float2half_rn(v - __half2float(hi));
    const int base = (k >> 5) * (2 * 32 * 264) + (k & 31) * 264 + p;
    g_C[base] = hi;
    g_C[base + 32 * 264] = lo;
}

__global__ void prep_k2_kernel(const float* __restrict__ M2,
                               const float* __restrict__ wgt) {
    const int p = threadIdx.x;       // 256 threads
    float s = 0.0f;
    #pragma unroll
    for (int k = 0; k < 32; k++) s += M2[p * 32 + k] * wgt[k];
    g_k2[p] = s;
}

// ---------------- A-chunk builder ----------------
// A[row][kk] = Y[row, k/65] * h[row, k%65], fp16 hi/lo, 80B-pitch rows.
__device__ __forceinline__ void build_A(char* smem, int c, int tid) {
    const int row = tid >> 2;
    const int kb = (tid & 3) * 8;
    const float* Yr = (const float*)(smem + SM_Y) + row * 12;
    const float* hr = (const float*)(smem + SM_H) + row * 66;
    uint32_t ph[4], pl[4];
    #pragma unroll
    for (int e2 = 0; e2 < 4; e2++) {
        __half h0, h1, l0, l1;
        #pragma unroll
        for (int s = 0; s < 2; s++) {
            const int k = c * 32 + kb + e2 * 2 + s;
            float v = 0.0f;
            if (k < K_RAW) {
                const int y = k / HLEN, j = k - y * HLEN;
                v = Yr[y] * hr[j];
            }
            __half hh = __float2half_rn(v);
            __half ll = __float2half_rn(v - __half2float(hh));
            if (s == 0) { h0 = hh; l0 = ll; } else { h1 = hh; l1 = ll; }
        }
        ph[e2] = hpack(h0, h1);
        pl[e2] = hpack(l0, l1);
    }
    char* base = smem + SM_A + (c & 1) * A_CHNK + row * AP + kb * 2;
    *(uint4*)base            = make_uint4(ph[0], ph[1], ph[2], ph[3]);
    *(uint4*)(base + A_PART) = make_uint4(pl[0], pl[1], pl[2], pl[3]);
}

// ---------------- main fused kernel ----------------
__global__ void __launch_bounds__(512, 1) fused_kernel(
    const float* __restrict__ r,
    const float* __restrict__ W1,
    const float* __restrict__ b1,
    float* __restrict__ out)
{
    extern __shared__ char smem[];
    const uint32_t sb = smem_u32(smem);
    const int tid = threadIdx.x, lane = tid & 31, wid = tid >> 5;
    const int wm = wid & 3, wn = wid >> 2;       // warp tile: m = wm*32, n = wn*64
    const int pbase = blockIdx.x * 128;

    // ---- prologue: start cp.async of B chunk 0 into buf 0 ----
    {
        const uint4* src = (const uint4*)g_C;
        #pragma unroll
        for (int i = 0; i < 5; i++) {
            const int idx = tid + 512 * i;
            if (idx < 2112) CP16(sb + SM_B + idx * 16, src + idx);
        }
        CP_COMMIT();
    }

    // ---- per-point math: rad, Y, h' ----
    if (tid < 128) {
        const int p = tid;
        const float x = r[(pbase + p) * 3 + 0];
        const float y = r[(pbase + p) * 3 + 1];
        const float z = r[(pbase + p) * 3 + 2];
        const float rad = sqrtf(x * x + y * y + z * z);
        ((float*)(smem + SM_RAD))[p] = rad;
        const float inv = 1.0f / fmaxf(rad, 1e-12f);
        const float ux = x * inv, uy = y * inv, uz = z * inv;
        float* Ys = (float*)(smem + SM_Y) + p * 12;
        Ys[0] = 0.28209479177387814f;
        Ys[1] = 0.4886025119029199f * uy;
        Ys[2] = 0.4886025119029199f * uz;
        Ys[3] = 0.4886025119029199f * ux;
        Ys[4] = 1.0925484305920792f * ux * uy;
        Ys[5] = 1.0925484305920792f * uy * uz;
        Ys[6] = 0.31539156525252005f * (3.0f * uz * uz - 1.0f);
        Ys[7] = 1.0925484305920792f * ux * uz;
        Ys[8] = 0.5462742152960396f * (ux * ux - uy * uy);
        float* hs = (float*)(smem + SM_H) + p * 66;
        #pragma unroll 8
        for (int j = 0; j < 64; j++)
            hs[j] = fmaxf(rad * W1[j] + b1[j], 0.0f);
        hs[64] = 1.0f;   // bias column (b2 folded into C)
        hs[65] = 0.0f;
    }
    CP_WAIT0();
    __syncthreads();

    build_A(smem, 0, tid);
    __syncthreads();

    float acc[2][8][4] = {};

    // lane-derived ldmatrix address pieces
    const uint32_t a_row  = (uint32_t)(lane & 15);
    const uint32_t a_byte = (uint32_t)((lane >> 4) * 16);
    const uint32_t b_krow = (uint32_t)((lane & 7) + ((lane >> 4) & 1) * 8);
    const uint32_t b_byte = (uint32_t)(((lane >> 3) & 1) * 16);

    #pragma unroll 2
    for (int c = 0; c < NCHUNK; c++) {
        if (c < NCHUNK - 1) {
            const uint4* src = (const uint4*)g_C + (c + 1) * 2112;
            const uint32_t dst = sb + SM_B + ((c + 1) & 1) * B_CHNK;
            #pragma unroll
            for (int i = 0; i < 5; i++) {
                const int idx = tid + 512 * i;
                if (idx < 2112) CP16(dst + idx * 16, src + idx);
            }
            CP_COMMIT();
            build_A(smem, c + 1, tid);
        }
        // ---- mma on chunk c ----
        const uint32_t Ab = sb + SM_A + (c & 1) * A_CHNK;
        const uint32_t Bb = sb + SM_B + (c & 1) * B_CHNK;
        #pragma unroll
        for (int q = 0; q < 2; q++) {
            uint32_t ah[2][4], al[2][4];
            #pragma unroll
            for (int mi = 0; mi < 2; mi++) {
                const uint32_t ra = Ab + (wm * 32 + mi * 16 + a_row) * AP + a_byte + q * 32;
                LDSM4(ah[mi], ra);
                LDSM4(al[mi], ra + A_PART);
            }
            #pragma unroll
            for (int nt = 0; nt < 4; nt++) {
                const uint32_t rb = Bb + (q * 16 + b_krow) * BP
                                  + (wn * 64 + nt * 16) * 2 + b_byte;
                uint32_t bh[4], bl[4];
                LDSM4T(bh, rb);
                LDSM4T(bl, rb + B_PART);
                #pragma unroll
                for (int mi = 0; mi < 2; mi++) {
                    MMA(acc[mi][nt * 2 + 0], ah[mi], bh[0], bh[2]);  // hi*hi
                    MMA(acc[mi][nt * 2 + 1], ah[mi], bh[1], bh[3]);
                    MMA(acc[mi][nt * 2 + 0], al[mi], bh[0], bh[2]);  // lo*hi
                    MMA(acc[mi][nt * 2 + 1], al[mi], bh[1], bh[3]);
                    MMA(acc[mi][nt * 2 + 0], ah[mi], bl[0], bl[2]);  // hi*lo
                    MMA(acc[mi][nt * 2 + 1], ah[mi], bl[1], bl[3]);
                }
            }
        }
        CP_WAIT0();
        __syncthreads();
    }

    // ---- epilogue: registers -> gmem, with mask / k2 fallback ----
    const float* radS = (const float*)(smem + SM_RAD);
    const int g = lane >> 2, tg = lane & 3;
    #pragma unroll
    for (int mi = 0; mi < 2; mi++) {
        const int row0 = wm * 32 + mi * 16 + g;
        const bool m0 = radS[row0] > 0.0f;
        const bool m1 = radS[row0 + 8] > 0.0f;
        #pragma unroll
        for (int ni = 0; ni < 8; ni++) {
            const int n = wn * 64 + ni * 8 + tg * 2;
            const float k20 = g_k2[n], k21 = g_k2[n + 1];
            float2 v0, v1;
            v0.x = m0 ? acc[mi][ni][0] : k20;
            v0.y = m0 ? acc[mi][ni][1] : k21;
            v1.x = m1 ? acc[mi][ni][2] : k20;
            v1.y = m1 ? acc[mi][ni][3] : k21;
            *(float2*)(out + (size_t)(pbase + row0) * 256 + n) = v0;
            *(float2*)(out + (size_t)(pbase + row0 + 8) * 256 + n) = v1;
        }
    }
}

// ---------------- launch ----------------
extern "C" void kernel_launch(void* const* d_in, const int* in_sizes, int n_in,
                              void* d_out, int out_size) {
    const float* r   = (const float*)d_in[0];
    const float* M1  = (const float*)d_in[1];
    const float* M2  = (const float*)d_in[2];
    const float* wgt = (const float*)d_in[3];
    const float* W1  = (const float*)d_in[4];
    const float* b1  = (const float*)d_in[5];
    const float* W2  = (const float*)d_in[6];
    const float* b2  = (const float*)d_in[7];

    prep_C_kernel<<<256, 608>>>(M1, W2, b2);
    prep_k2_kernel<<<1, 256>>>(M2, wgt);

    (void)cudaFuncSetAttribute(fused_kernel,
                               cudaFuncAttributeMaxDynamicSharedMemorySize, SM_TOTAL);
    fused_kernel<<<N_PTS / 128, 512, SM_TOTAL>>>(r, W1, b1, (float*)d_out);
}

// round 16
// speedup vs baseline: 1.0115x; 1.0115x over previous
#include <cuda_runtime.h>
#include <cuda_fp16.h>
#include <stdint.h>

// ---------------- problem constants ----------------
#define N_PTS   131072
#define K_RAW   585            // 9 * 65 (Y x [h,1] outer product)
#define NCHUNK  19             // 19 * 32 = 608 = K padded
#define HLEN    65

// ---------------- smem layout ----------------
#define BP      528            // B row pitch bytes (264 halves)
#define B_PART  16896          // 32*528
#define B_CHNK  33792          // 2 parts
#define AP      80
#define A_PART  10240          // 128*80
#define A_CHNK  20480
#define SM_B    0              // 2*33792 = 67584
#define SM_A    67584          // 2*20480 = 40960
#define SM_H    108544         // fp32 [128][66] = 33792
#define SM_Y    142336         // fp32 [128][12] = 6144
#define SM_RAD  148480         // fp32 [128]     = 512
#define SM_TOTAL 148992

// ---------------- persistent scratch ----------------
__device__ __align__(16) __half g_C[NCHUNK * 2 * 32 * 264];
__device__ float g_k2[256];

// ---------------- PTX helpers ----------------
__device__ __forceinline__ uint32_t smem_u32(const void* p) {
    uint32_t a;
    asm("{ .reg .u64 t; cvta.to.shared.u64 t, %1; cvt.u32.u64 %0, t; }" : "=r"(a) : "l"(p));
    return a;
}
__device__ __forceinline__ uint32_t hpack(__half a, __half b) {
    return (uint32_t)__half_as_ushort(a) | ((uint32_t)__half_as_ushort(b) << 16);
}
#define CP16(dst, src) asm volatile("cp.async.cg.shared.global [%0], [%1], 16;" :: "r"(dst), "l"(src) : "memory")
#define CP_COMMIT()    asm volatile("cp.async.commit_group;" ::: "memory")
#define CP_WAIT0()     asm volatile("cp.async.wait_group 0;" ::: "memory")

#define LDSM4(r, a) \
    asm volatile("ldmatrix.sync.aligned.m8n8.x4.shared.b16 {%0,%1,%2,%3}, [%4];" \
        : "=r"((r)[0]), "=r"((r)[1]), "=r"((r)[2]), "=r"((r)[3]) : "r"(a))
#define LDSM4T(r, a) \
    asm volatile("ldmatrix.sync.aligned.m8n8.x4.trans.shared.b16 {%0,%1,%2,%3}, [%4];" \
        : "=r"((r)[0]), "=r"((r)[1]), "=r"((r)[2]), "=r"((r)[3]) : "r"(a))
// NOTE: non-volatile — pure register op; lets ptxas schedule MMAs to hide latency.
#define MMA(d, a, b0v, b1v) \
    asm("mma.sync.aligned.m16n8k16.row.col.f32.f16.f16.f32 " \
        "{%0,%1,%2,%3},{%4,%5,%6,%7},{%8,%9},{%0,%1,%2,%3};" \
        : "+f"((d)[0]), "+f"((d)[1]), "+f"((d)[2]), "+f"((d)[3]) \
        : "r"((a)[0]), "r"((a)[1]), "r"((a)[2]), "r"((a)[3]), "r"(b0v), "r"(b1v))

// ---------------- prep kernel (merged: C + k2) ----------------
// C[p, y*65+j] = sum_w W2[j,w]*M1[p, y*96+w]  (j<64);  j==64 -> b2 row.
// Stored fp16 hi/lo, [k][n=p] layout, 528B pitch, chunked by 32 k.
// Also: g_k2[p] = sum_k M2[p,k]*wgt[k]  (thread 0 of each block).
__global__ void prep_kernel(const float* __restrict__ M1,
                            const float* __restrict__ W2,
                            const float* __restrict__ b2,
                            const float* __restrict__ M2,
                            const float* __restrict__ wgt) {
    __shared__ float sW2[64 * 96];
    __shared__ float sb2[96];
    __shared__ float sM1[864];
    const int p = blockIdx.x;        // 0..255
    const int t = threadIdx.x;       // 0..607
    for (int i = t; i < 64 * 96; i += 608) sW2[i] = W2[i];
    if (t < 96) sb2[t] = b2[t];
    for (int i = t; i < 864; i += 608) sM1[i] = M1[p * 864 + i];
    if (t == 0) {
        float s = 0.0f;
        #pragma unroll
        for (int k = 0; k < 32; k++) s += M2[p * 32 + k] * wgt[k];
        g_k2[p] = s;
    }
    __syncthreads();
    const int k = t;                 // 0..607
    float v = 0.0f;
    if (k < K_RAW) {
        const int y = k / HLEN, j = k - y * HLEN;
        const float* m = sM1 + y * 96;
        const float* w = (j < 64) ? (sW2 + j * 96) : sb2;
        #pragma unroll 8
        for (int wi = 0; wi < 96; wi++) v += w[wi] * m[wi];
    }
    __half hi = __float2half_rn(v);
    __half lo = __float2half_rn(v - __half2float(hi));
    const int base = (k >> 5) * (2 * 32 * 264) + (k & 31) * 264 + p;
    g_C[base] = hi;
    g_C[base + 32 * 264] = lo;
}

// ---------------- A-chunk builder ----------------
__device__ __forceinline__ void build_A(char* smem, int c, int tid) {
    const int row = tid >> 2;
    const int kb = (tid & 3) * 8;
    const float* Yr = (const float*)(smem + SM_Y) + row * 12;
    const float* hr = (const float*)(smem + SM_H) + row * 66;
    uint32_t ph[4], pl[4];
    #pragma unroll
    for (int e2 = 0; e2 < 4; e2++) {
        __half h0, h1, l0, l1;
        #pragma unroll
        for (int s = 0; s < 2; s++) {
            const int k = c * 32 + kb + e2 * 2 + s;
            float v = 0.0f;
            if (k < K_RAW) {
                const int y = k / HLEN, j = k - y * HLEN;
                v = Yr[y] * hr[j];
            }
            __half hh = __float2half_rn(v);
            __half ll = __float2half_rn(v - __half2float(hh));
            if (s == 0) { h0 = hh; l0 = ll; } else { h1 = hh; l1 = ll; }
        }
        ph[e2] = hpack(h0, h1);
        pl[e2] = hpack(l0, l1);
    }
    char* base = smem + SM_A + (c & 1) * A_CHNK + row * AP + kb * 2;
    *(uint4*)base            = make_uint4(ph[0], ph[1], ph[2], ph[3]);
    *(uint4*)(base + A_PART) = make_uint4(pl[0], pl[1], pl[2], pl[3]);
}

// ---------------- main fused kernel ----------------
__global__ void __launch_bounds__(512, 1) fused_kernel(
    const float* __restrict__ r,
    const float* __restrict__ W1,
    const float* __restrict__ b1,
    float* __restrict__ out)
{
    extern __shared__ char smem[];
    const uint32_t sb = smem_u32(smem);
    const int tid = threadIdx.x, lane = tid & 31, wid = tid >> 5;
    const int wm = wid & 3, wn = wid >> 2;       // warp tile: m = wm*32, n = wn*64
    const int pbase = blockIdx.x * 128;

    // ---- prologue: start cp.async of B chunk 0 into buf 0 ----
    {
        const uint4* src = (const uint4*)g_C;
        #pragma unroll
        for (int i = 0; i < 5; i++) {
            const int idx = tid + 512 * i;
            if (idx < 2112) CP16(sb + SM_B + idx * 16, src + idx);
        }
        CP_COMMIT();
    }

    // ---- per-point math: rad, Y, h' ----
    if (tid < 128) {
        const int p = tid;
        const float x = r[(pbase + p) * 3 + 0];
        const float y = r[(pbase + p) * 3 + 1];
        const float z = r[(pbase + p) * 3 + 2];
        const float rad = sqrtf(x * x + y * y + z * z);
        ((float*)(smem + SM_RAD))[p] = rad;
        const float inv = 1.0f / fmaxf(rad, 1e-12f);
        const float ux = x * inv, uy = y * inv, uz = z * inv;
        float* Ys = (float*)(smem + SM_Y) + p * 12;
        Ys[0] = 0.28209479177387814f;
        Ys[1] = 0.4886025119029199f * uy;
        Ys[2] = 0.4886025119029199f * uz;
        Ys[3] = 0.4886025119029199f * ux;
        Ys[4] = 1.0925484305920792f * ux * uy;
        Ys[5] = 1.0925484305920792f * uy * uz;
        Ys[6] = 0.31539156525252005f * (3.0f * uz * uz - 1.0f);
        Ys[7] = 1.0925484305920792f * ux * uz;
        Ys[8] = 0.5462742152960396f * (ux * ux - uy * uy);
        float* hs = (float*)(smem + SM_H) + p * 66;
        #pragma unroll 8
        for (int j = 0; j < 64; j++)
            hs[j] = fmaxf(rad * W1[j] + b1[j], 0.0f);
        hs[64] = 1.0f;   // bias column (b2 folded into C)
        hs[65] = 0.0f;
    }
    CP_WAIT0();
    __syncthreads();

    build_A(smem, 0, tid);
    __syncthreads();

    float acc[2][8][4] = {};

    // lane-derived ldmatrix address pieces
    const uint32_t a_row  = (uint32_t)(lane & 15);
    const uint32_t a_byte = (uint32_t)((lane >> 4) * 16);
    const uint32_t b_krow = (uint32_t)((lane & 7) + ((lane >> 4) & 1) * 8);
    const uint32_t b_byte = (uint32_t)(((lane >> 3) & 1) * 16);

    #pragma unroll 2
    for (int c = 0; c < NCHUNK; c++) {
        if (c < NCHUNK - 1) {
            const uint4* src = (const uint4*)g_C + (c + 1) * 2112;
            const uint32_t dst = sb + SM_B + ((c + 1) & 1) * B_CHNK;
            #pragma unroll
            for (int i = 0; i < 5; i++) {
                const int idx = tid + 512 * i;
                if (idx < 2112) CP16(dst + idx * 16, src + idx);
            }
            CP_COMMIT();
            build_A(smem, c + 1, tid);
        }
        // ---- mma on chunk c ----
        const uint32_t Ab = sb + SM_A + (c & 1) * A_CHNK;
        const uint32_t Bb = sb + SM_B + (c & 1) * B_CHNK;
        #pragma unroll
        for (int q = 0; q < 2; q++) {
            uint32_t ah[2][4], al[2][4];
            #pragma unroll
            for (int mi = 0; mi < 2; mi++) {
                const uint32_t ra = Ab + (wm * 32 + mi * 16 + a_row) * AP + a_byte + q * 32;
                LDSM4(ah[mi], ra);
                LDSM4(al[mi], ra + A_PART);
            }
            #pragma unroll
            for (int nt = 0; nt < 4; nt++) {
                const uint32_t rb = Bb + (q * 16 + b_krow) * BP
                                  + (wn * 64 + nt * 16) * 2 + b_byte;
                uint32_t bh[4], bl[4];
                LDSM4T(bh, rb);
                LDSM4T(bl, rb + B_PART);
                // term-major ordering: same-accumulator dependency distance = 4
                MMA(acc[0][nt * 2 + 0], ah[0], bh[0], bh[2]);  // hi*hi
                MMA(acc[0][nt * 2 + 1], ah[0], bh[1], bh[3]);
                MMA(acc[1][nt * 2 + 0], ah[1], bh[0], bh[2]);
                MMA(acc[1][nt * 2 + 1], ah[1], bh[1], bh[3]);
                MMA(acc[0][nt * 2 + 0], al[0], bh[0], bh[2]);  // lo*hi
                MMA(acc[0][nt * 2 + 1], al[0], bh[1], bh[3]);
                MMA(acc[1][nt * 2 + 0], al[1], bh[0], bh[2]);
                MMA(acc[1][nt * 2 + 1], al[1], bh[1], bh[3]);
                MMA(acc[0][nt * 2 + 0], ah[0], bl[0], bl[2]);  // hi*lo
                MMA(acc[0][nt * 2 + 1], ah[0], bl[1], bl[3]);
                MMA(acc[1][nt * 2 + 0], ah[1], bl[0], bl[2]);
                MMA(acc[1][nt * 2 + 1], ah[1], bl[1], bl[3]);
            }
        }
        CP_WAIT0();
        __syncthreads();
    }

    // ---- epilogue: registers -> gmem, with mask / k2 fallback ----
    const float* radS = (const float*)(smem + SM_RAD);
    const int g = lane >> 2, tg = lane & 3;
    #pragma unroll
    for (int mi = 0; mi < 2; mi++) {
        const int row0 = wm * 32 + mi * 16 + g;
        const bool m0 = radS[row0] > 0.0f;
        const bool m1 = radS[row0 + 8] > 0.0f;
        #pragma unroll
        for (int ni = 0; ni < 8; ni++) {
            const int n = wn * 64 + ni * 8 + tg * 2;
            const float k20 = g_k2[n], k21 = g_k2[n + 1];
            float2 v0, v1;
            v0.x = m0 ? acc[mi][ni][0] : k20;
            v0.y = m0 ? acc[mi][ni][1] : k21;
            v1.x = m1 ? acc[mi][ni][2] : k20;
            v1.y = m1 ? acc[mi][ni][3] : k21;
            *(float2*)(out + (size_t)(pbase + row0) * 256 + n) = v0;
            *(float2*)(out + (size_t)(pbase + row0 + 8) * 256 + n) = v1;
        }
    }
}

// ---------------- launch ----------------
extern "C" void kernel_launch(void* const* d_in, const int* in_sizes, int n_in,
                              void* d_out, int out_size) {
    const float* r   = (const float*)d_in[0];
    const float* M1  = (const float*)d_in[1];
    const float* M2  = (const float*)d_in[2];
    const float* wgt = (const float*)d_in[3];
    const float* W1  = (const float*)d_in[4];
    const float* b1  = (const float*)d_in[5];
    const float* W2  = (const float*)d_in[6];
    const float* b2  = (const float*)d_in[7];

    prep_kernel<<<256, 608>>>(M1, W2, b2, M2, wgt);

    (void)cudaFuncSetAttribute(fused_kernel,
                               cudaFuncAttributeMaxDynamicSharedMemorySize, SM_TOTAL);
    fused_kernel<<<N_PTS / 128, 512, SM_TOTAL>>>(r, W1, b1, (float*)d_out);
}